// round 7
// baseline (speedup 1.0000x reference)
#include <cuda_runtime.h>

#define N_NODES 50000
#define N_EDGES 800000
#define DIM_IN  128
#define DIM_HID 256
#define DIM_OUT 128
#define SCAN_B  512
#define SCAN_NB 98   // ceil(50000/512)

// ---------------- scratch (no allocations allowed) ----------------
__device__ __align__(16) float g_bufA[N_NODES * DIM_HID];   // 51.2 MB
__device__ __align__(16) float g_bufB[N_NODES * DIM_HID];   // 51.2 MB
__device__ float g_deg[N_NODES];
__device__ float g_dinv[N_NODES];
__device__ int   g_count[N_NODES];
__device__ int   g_indptr[N_NODES];
__device__ int   g_cursor[N_NODES];
__device__ int   g_blocksums[SCAN_NB];
__device__ int   g_esrc[N_EDGES];
__device__ float g_enorm[N_EDGES];
__device__ int   g_i64;          // 1 if edge_index is int64, 0 if int32

__device__ __forceinline__ int clampi(int v) {
    return min(max(v, 0), N_NODES - 1);
}

// read edge endpoint j (0=row,1=col) of edge e under detected dtype
__device__ __forceinline__ int eidx(const void* ei, int j, int e) {
    if (g_i64) return clampi((int)((const long long*)ei)[j * N_EDGES + e]);
    return clampi(((const int*)ei)[j * N_EDGES + e]);
}

// ---------------- dtype detection ----------------
// int64 indices < 2^31  => every odd int32 word is 0.
// int32 indices          => odd words are random values in [0,50000).
__global__ void k_detect(const int* __restrict__ ei32) {
    __shared__ int s_nz;
    if (threadIdx.x == 0) s_nz = 0;
    __syncthreads();
    int nz = 0;
    for (int t = threadIdx.x; t < 2048; t += blockDim.x)
        if (ei32[2 * t + 1] != 0) nz = 1;
    if (nz) atomicOr(&s_nz, 1);
    __syncthreads();
    if (threadIdx.x == 0) g_i64 = (s_nz == 0) ? 1 : 0;
}

// ---------------- graph build ----------------
__global__ void k_init() {
    int i = blockIdx.x * blockDim.x + threadIdx.x;
    if (i < N_NODES) { g_deg[i] = 1.0f; g_count[i] = 0; }  // self-loop weight 1
}

__global__ void k_degcount(const void* __restrict__ ei,
                           const float* __restrict__ ew) {
    int e = blockIdx.x * blockDim.x + threadIdx.x;
    if (e < N_EDGES) {
        int c = eidx(ei, 1, e);
        atomicAdd(&g_deg[c], ew[e]);
        atomicAdd(&g_count[c], 1);
    }
}

__global__ void k_dinv() {
    int i = blockIdx.x * blockDim.x + threadIdx.x;
    if (i < N_NODES) g_dinv[i] = rsqrtf(g_deg[i]);   // deg >= 1 always
}

__global__ void k_scan1() {
    __shared__ int sh[SCAN_B];
    int tid = threadIdx.x;
    int i = blockIdx.x * SCAN_B + tid;
    int v = (i < N_NODES) ? g_count[i] : 0;
    sh[tid] = v;
    __syncthreads();
    #pragma unroll
    for (int off = 1; off < SCAN_B; off <<= 1) {
        int t = (tid >= off) ? sh[tid - off] : 0;
        __syncthreads();
        sh[tid] += t;
        __syncthreads();
    }
    if (i < N_NODES) g_indptr[i] = sh[tid] - v;   // exclusive
    if (tid == SCAN_B - 1) g_blocksums[blockIdx.x] = sh[SCAN_B - 1];
}

__global__ void k_scan2() {
    if (threadIdx.x == 0) {
        int s = 0;
        for (int b = 0; b < SCAN_NB; b++) {
            int t = g_blocksums[b];
            g_blocksums[b] = s;
            s += t;
        }
    }
}

__global__ void k_scan3() {
    int i = blockIdx.x * blockDim.x + threadIdx.x;
    if (i < N_NODES) {
        int p = g_indptr[i] + g_blocksums[i >> 9];
        g_indptr[i] = p;
        g_cursor[i] = p;
    }
}

__global__ void k_scatter(const void* __restrict__ ei,
                          const float* __restrict__ ew) {
    int e = blockIdx.x * blockDim.x + threadIdx.x;
    if (e < N_EDGES) {
        int r = eidx(ei, 0, e);
        int c = eidx(ei, 1, e);
        int pos = atomicAdd(&g_cursor[c], 1);
        g_esrc[pos] = r;
        g_enorm[pos] = g_dinv[r] * ew[e] * g_dinv[c];
    }
}

// ---------------- aggregation: out[n] = dinv[n]^2*src[n] + sum_e norm*src[src_e]
// warp per destination node, V float4 per lane (dim = V*128)
template <int V>
__global__ void k_agg(const float* __restrict__ src, float* __restrict__ dst) {
    int gw = (blockIdx.x * blockDim.x + threadIdx.x) >> 5;
    int lane = threadIdx.x & 31;
    if (gw >= N_NODES) return;
    const float4* s4 = (const float4*)src;
    const int rs = V * 32;                 // float4 row stride
    float dn = g_dinv[gw];
    float sw = dn * dn;
    float4 acc[V];
    #pragma unroll
    for (int v = 0; v < V; v++) {
        float4 t = s4[gw * rs + v * 32 + lane];
        acc[v].x = sw * t.x; acc[v].y = sw * t.y;
        acc[v].z = sw * t.z; acc[v].w = sw * t.w;
    }
    int i = g_indptr[gw];
    int end = i + g_count[gw];
    for (; i + 2 <= end; i += 2) {          // 2x unroll for MLP
        int r0 = g_esrc[i], r1 = g_esrc[i + 1];
        float w0 = g_enorm[i], w1 = g_enorm[i + 1];
        #pragma unroll
        for (int v = 0; v < V; v++) {
            float4 t0 = s4[r0 * rs + v * 32 + lane];
            float4 t1 = s4[r1 * rs + v * 32 + lane];
            acc[v].x += w0 * t0.x + w1 * t1.x;
            acc[v].y += w0 * t0.y + w1 * t1.y;
            acc[v].z += w0 * t0.z + w1 * t1.z;
            acc[v].w += w0 * t0.w + w1 * t1.w;
        }
    }
    if (i < end) {
        int r0 = g_esrc[i];
        float w0 = g_enorm[i];
        #pragma unroll
        for (int v = 0; v < V; v++) {
            float4 t0 = s4[r0 * rs + v * 32 + lane];
            acc[v].x += w0 * t0.x; acc[v].y += w0 * t0.y;
            acc[v].z += w0 * t0.z; acc[v].w += w0 * t0.w;
        }
    }
    float4* d4 = (float4*)dst;
    #pragma unroll
    for (int v = 0; v < V; v++) d4[gw * rs + v * 32 + lane] = acc[v];
}

// ---------------- GEMM: C[M,NC] = A[M,K] @ W[K,NC]  (+fused bias/BN/ReLU)
// BM=128, BN=64, BK=16, 256 threads, 8x4 per thread
__global__ __launch_bounds__(256) void k_gemm(
    const float* __restrict__ A, const float* __restrict__ W,
    float* __restrict__ C, int M, int K, int NC,
    const float* __restrict__ bias, const float* __restrict__ bng,
    const float* __restrict__ bnb, int mode)   // mode 0: plain, 1: bias+BN+ReLU
{
    __shared__ float As[16][132];
    __shared__ float Bs[16][64];
    int tx = threadIdx.x & 15;
    int ty = threadIdx.x >> 4;
    int m0 = blockIdx.x * 128;
    int n0 = blockIdx.y * 64;
    int K4 = K >> 2, NC4 = NC >> 2;
    const float4* A4 = (const float4*)A;
    const float4* W4 = (const float4*)W;
    float acc[8][4];
    #pragma unroll
    for (int i = 0; i < 8; i++)
        #pragma unroll
        for (int j = 0; j < 4; j++) acc[i][j] = 0.f;

    for (int kt = 0; kt < K; kt += 16) {
        #pragma unroll
        for (int l = 0; l < 2; l++) {
            int fid = threadIdx.x + l * 256;      // 0..511
            int m = fid >> 2;
            int kq = fid & 3;
            int gm = m0 + m;
            float4 a = make_float4(0.f, 0.f, 0.f, 0.f);
            if (gm < M) a = A4[gm * K4 + (kt >> 2) + kq];
            As[kq * 4 + 0][m] = a.x;
            As[kq * 4 + 1][m] = a.y;
            As[kq * 4 + 2][m] = a.z;
            As[kq * 4 + 3][m] = a.w;
        }
        {
            int kr = threadIdx.x >> 4;            // 0..15
            int nq = threadIdx.x & 15;            // 0..15
            float4 b = W4[(kt + kr) * NC4 + (n0 >> 2) + nq];
            *(float4*)&Bs[kr][nq * 4] = b;
        }
        __syncthreads();
        #pragma unroll
        for (int k = 0; k < 16; k++) {
            float ar[8], br[4];
            *(float4*)&ar[0] = *(float4*)&As[k][ty * 8];
            *(float4*)&ar[4] = *(float4*)&As[k][ty * 8 + 4];
            *(float4*)&br[0] = *(float4*)&Bs[k][tx * 4];
            #pragma unroll
            for (int i = 0; i < 8; i++)
                #pragma unroll
                for (int j = 0; j < 4; j++)
                    acc[i][j] = fmaf(ar[i], br[j], acc[i][j]);
        }
        __syncthreads();
    }

    int gn = n0 + tx * 4;
    float bi[4] = {0.f, 0.f, 0.f, 0.f}, sc[4], bb[4];
    if (mode == 1) {
        float inv = rsqrtf(1.0f + 1e-5f);
        #pragma unroll
        for (int j = 0; j < 4; j++) {
            bi[j] = bias[gn + j];
            sc[j] = bng[gn + j] * inv;
            bb[j] = bnb[gn + j];
        }
    }
    float4* C4 = (float4*)C;
    #pragma unroll
    for (int i = 0; i < 8; i++) {
        int gm = m0 + ty * 8 + i;
        if (gm < M) {
            float4 c;
            c.x = acc[i][0]; c.y = acc[i][1]; c.z = acc[i][2]; c.w = acc[i][3];
            if (mode == 1) {
                c.x = fmaxf(fmaf(c.x + bi[0], sc[0], bb[0]), 0.f);
                c.y = fmaxf(fmaf(c.y + bi[1], sc[1], bb[1]), 0.f);
                c.z = fmaxf(fmaf(c.z + bi[2], sc[2], bb[2]), 0.f);
                c.w = fmaxf(fmaf(c.w + bi[3], sc[3], bb[3]), 0.f);
            }
            C4[gm * NC4 + (gn >> 2)] = c;
        }
    }
}

// ---------------- log_softmax over 128 cols, warp per row, +final bias
__global__ void k_logsoftmax(const float* __restrict__ in,
                             const float* __restrict__ bl,
                             float* __restrict__ out) {
    int gw = (blockIdx.x * blockDim.x + threadIdx.x) >> 5;
    int lane = threadIdx.x & 31;
    if (gw >= N_NODES) return;
    float4 v = ((const float4*)in)[gw * 32 + lane];
    float4 b = ((const float4*)bl)[lane];
    v.x += b.x; v.y += b.y; v.z += b.z; v.w += b.w;
    float m = fmaxf(fmaxf(v.x, v.y), fmaxf(v.z, v.w));
    #pragma unroll
    for (int o = 16; o; o >>= 1) m = fmaxf(m, __shfl_xor_sync(0xFFFFFFFFu, m, o));
    float s = expf(v.x - m) + expf(v.y - m) + expf(v.z - m) + expf(v.w - m);
    #pragma unroll
    for (int o = 16; o; o >>= 1) s += __shfl_xor_sync(0xFFFFFFFFu, s, o);
    float lse = m + logf(s);
    float4 o4;
    o4.x = v.x - lse; o4.y = v.y - lse; o4.z = v.z - lse; o4.w = v.w - lse;
    ((float4*)out)[gw * 32 + lane] = o4;
}

// ---------------- driver ----------------
extern "C" void kernel_launch(void* const* d_in, const int* in_sizes, int n_in,
                              void* d_out, int out_size) {
    const float* x   = (const float*)d_in[0];
    const void*  ei  = d_in[1];                 // int32 or int64, detected on device
    const float* ew  = (const float*)d_in[2];
    const float* W0  = (const float*)d_in[3];
    const float* b0  = (const float*)d_in[4];
    const float* W1  = (const float*)d_in[5];
    const float* b1  = (const float*)d_in[6];
    const float* Wl  = (const float*)d_in[7];
    const float* bl  = (const float*)d_in[8];
    const float* g0  = (const float*)d_in[9];
    const float* be0 = (const float*)d_in[10];
    const float* g1  = (const float*)d_in[11];
    const float* be1 = (const float*)d_in[12];
    float* out = (float*)d_out;

    float* bufA = nullptr;
    float* bufB = nullptr;
    cudaGetSymbolAddress((void**)&bufA, g_bufA);
    cudaGetSymbolAddress((void**)&bufB, g_bufB);

    const int NB_N = (N_NODES + 255) / 256;
    const int NB_E = (N_EDGES + 255) / 256;
    const int NB_W = (N_NODES * 32 + 255) / 256;   // warp-per-node grids

    // dtype probe + graph build (deterministic work every launch)
    k_detect<<<1, 1024>>>((const int*)ei);
    k_init<<<NB_N, 256>>>();
    k_degcount<<<NB_E, 256>>>(ei, ew);
    k_dinv<<<NB_N, 256>>>();
    k_scan1<<<SCAN_NB, SCAN_B>>>();
    k_scan2<<<1, 32>>>();
    k_scan3<<<NB_N, 256>>>();
    k_scatter<<<NB_E, 256>>>(ei, ew);

    // layer 0: agg(x) [N,128] -> bufA; GEMM 128->256 (+b0, BN0, ReLU) -> bufB
    k_agg<1><<<NB_W, 256>>>(x, bufA);
    k_gemm<<<dim3((N_NODES + 127) / 128, DIM_HID / 64), 256>>>(
        bufA, W0, bufB, N_NODES, DIM_IN, DIM_HID, b0, g0, be0, 1);

    // layer 1: agg(bufB) [N,256] -> bufA; GEMM 256->256 (+b1, BN1, ReLU) -> bufB
    k_agg<2><<<NB_W, 256>>>(bufB, bufA);
    k_gemm<<<dim3((N_NODES + 127) / 128, DIM_HID / 64), 256>>>(
        bufA, W1, bufB, N_NODES, DIM_HID, DIM_HID, b1, g1, be1, 1);

    // layer 2: GEMM 256->128 (plain) bufB->bufA; agg at dim 128 bufA->bufB
    k_gemm<<<dim3((N_NODES + 127) / 128, DIM_OUT / 64), 256>>>(
        bufB, Wl, bufA, N_NODES, DIM_HID, DIM_OUT, nullptr, nullptr, nullptr, 0);
    k_agg<1><<<NB_W, 256>>>(bufA, bufB);

    // +bl and log_softmax
    k_logsoftmax<<<NB_W, 256>>>(bufB, bl, out);
}

// round 11
// speedup vs baseline: 1.4817x; 1.4817x over previous
#include <cuda_runtime.h>
#include <cstdint>

#define N_NODES 50000
#define N_EDGES 800000
#define DIM_IN  128
#define DIM_HID 256
#define DIM_OUT 128
#define SCAN_B  512
#define SCAN_NB 98   // ceil(50000/512)

// ---------------- scratch (no allocations allowed) ----------------
__device__ __align__(16) float g_bufA[N_NODES * DIM_HID];   // 51.2 MB
__device__ __align__(16) float g_bufB[N_NODES * DIM_HID];   // 51.2 MB
__device__ __align__(16) float g_wt[DIM_HID * DIM_HID];     // transposed weights
__device__ float g_deg[N_NODES];
__device__ float g_dinv[N_NODES];
__device__ int   g_count[N_NODES];
__device__ int   g_indptr[N_NODES];
__device__ int   g_cursor[N_NODES];
__device__ int   g_blocksums[SCAN_NB];
__device__ int   g_esrc[N_EDGES];
__device__ float g_enorm[N_EDGES];
__device__ int   g_i64;          // 1 if edge_index is int64, 0 if int32

__device__ __forceinline__ int clampi(int v) {
    return min(max(v, 0), N_NODES - 1);
}
__device__ __forceinline__ int eidx(const void* ei, int j, int e) {
    if (g_i64) return clampi((int)((const long long*)ei)[j * N_EDGES + e]);
    return clampi(((const int*)ei)[j * N_EDGES + e]);
}

__device__ __forceinline__ uint32_t f2tf32(float f) {
    uint32_t o;
    asm("cvt.rna.tf32.f32 %0, %1;" : "=r"(o) : "f"(f));
    return o;
}
__device__ __forceinline__ void mma_tf32(float* c, const uint32_t* a, const uint32_t* b) {
    asm volatile(
        "mma.sync.aligned.m16n8k8.row.col.f32.tf32.tf32.f32 "
        "{%0,%1,%2,%3}, {%4,%5,%6,%7}, {%8,%9}, {%0,%1,%2,%3};"
        : "+f"(c[0]), "+f"(c[1]), "+f"(c[2]), "+f"(c[3])
        : "r"(a[0]), "r"(a[1]), "r"(a[2]), "r"(a[3]), "r"(b[0]), "r"(b[1]));
}

// ---------------- dtype detection ----------------
__global__ void k_detect(const int* __restrict__ ei32) {
    __shared__ int s_nz;
    if (threadIdx.x == 0) s_nz = 0;
    __syncthreads();
    int nz = 0;
    for (int t = threadIdx.x; t < 2048; t += blockDim.x)
        if (ei32[2 * t + 1] != 0) nz = 1;
    if (nz) atomicOr(&s_nz, 1);
    __syncthreads();
    if (threadIdx.x == 0) g_i64 = (s_nz == 0) ? 1 : 0;
}

// ---------------- graph build ----------------
__global__ void k_init() {
    int i = blockIdx.x * blockDim.x + threadIdx.x;
    if (i < N_NODES) { g_deg[i] = 1.0f; g_count[i] = 0; }
}

__global__ void k_degcount(const void* __restrict__ ei,
                           const float* __restrict__ ew) {
    int e = blockIdx.x * blockDim.x + threadIdx.x;
    if (e < N_EDGES) {
        int c = eidx(ei, 1, e);
        atomicAdd(&g_deg[c], ew[e]);
        atomicAdd(&g_count[c], 1);
    }
}

__global__ void k_dinv() {
    int i = blockIdx.x * blockDim.x + threadIdx.x;
    if (i < N_NODES) g_dinv[i] = rsqrtf(g_deg[i]);
}

__global__ void k_scan1() {
    __shared__ int sh[SCAN_B];
    int tid = threadIdx.x;
    int i = blockIdx.x * SCAN_B + tid;
    int v = (i < N_NODES) ? g_count[i] : 0;
    sh[tid] = v;
    __syncthreads();
    #pragma unroll
    for (int off = 1; off < SCAN_B; off <<= 1) {
        int t = (tid >= off) ? sh[tid - off] : 0;
        __syncthreads();
        sh[tid] += t;
        __syncthreads();
    }
    if (i < N_NODES) g_indptr[i] = sh[tid] - v;
    if (tid == SCAN_B - 1) g_blocksums[blockIdx.x] = sh[SCAN_B - 1];
}

__global__ void k_scan2() {
    if (threadIdx.x == 0) {
        int s = 0;
        for (int b = 0; b < SCAN_NB; b++) {
            int t = g_blocksums[b];
            g_blocksums[b] = s;
            s += t;
        }
    }
}

__global__ void k_scan3() {
    int i = blockIdx.x * blockDim.x + threadIdx.x;
    if (i < N_NODES) {
        int p = g_indptr[i] + g_blocksums[i >> 9];
        g_indptr[i] = p;
        g_cursor[i] = p;
    }
}

__global__ void k_scatter(const void* __restrict__ ei,
                          const float* __restrict__ ew) {
    int e = blockIdx.x * blockDim.x + threadIdx.x;
    if (e < N_EDGES) {
        int r = eidx(ei, 0, e);
        int c = eidx(ei, 1, e);
        int pos = atomicAdd(&g_cursor[c], 1);
        g_esrc[pos] = r;
        g_enorm[pos] = g_dinv[r] * ew[e] * g_dinv[c];
    }
}

// ---------------- aggregation (warp per node, V float4 per lane) ----------------
template <int V>
__global__ void k_agg(const float* __restrict__ src, float* __restrict__ dst) {
    int gw = (blockIdx.x * blockDim.x + threadIdx.x) >> 5;
    int lane = threadIdx.x & 31;
    if (gw >= N_NODES) return;
    const float4* s4 = (const float4*)src;
    const int rs = V * 32;
    float dn = g_dinv[gw];
    float sw = dn * dn;
    float4 acc[V];
    #pragma unroll
    for (int v = 0; v < V; v++) {
        float4 t = s4[gw * rs + v * 32 + lane];
        acc[v].x = sw * t.x; acc[v].y = sw * t.y;
        acc[v].z = sw * t.z; acc[v].w = sw * t.w;
    }
    int i = g_indptr[gw];
    int end = i + g_count[gw];
    for (; i + 2 <= end; i += 2) {
        int r0 = g_esrc[i], r1 = g_esrc[i + 1];
        float w0 = g_enorm[i], w1 = g_enorm[i + 1];
        #pragma unroll
        for (int v = 0; v < V; v++) {
            float4 t0 = s4[r0 * rs + v * 32 + lane];
            float4 t1 = s4[r1 * rs + v * 32 + lane];
            acc[v].x += w0 * t0.x + w1 * t1.x;
            acc[v].y += w0 * t0.y + w1 * t1.y;
            acc[v].z += w0 * t0.z + w1 * t1.z;
            acc[v].w += w0 * t0.w + w1 * t1.w;
        }
    }
    if (i < end) {
        int r0 = g_esrc[i];
        float w0 = g_enorm[i];
        #pragma unroll
        for (int v = 0; v < V; v++) {
            float4 t0 = s4[r0 * rs + v * 32 + lane];
            acc[v].x += w0 * t0.x; acc[v].y += w0 * t0.y;
            acc[v].z += w0 * t0.z; acc[v].w += w0 * t0.w;
        }
    }
    float4* d4 = (float4*)dst;
    #pragma unroll
    for (int v = 0; v < V; v++) d4[gw * rs + v * 32 + lane] = acc[v];
}

// ---------------- weight transpose: Wt[NC][K] = W[K][NC] ----------------
__global__ void k_transpose(const float* __restrict__ W, int K, int NC) {
    __shared__ float t[32][33];
    int bx = blockIdx.x * 32;   // k block
    int by = blockIdx.y * 32;   // n block
    int x = threadIdx.x, y = threadIdx.y;
    for (int i = y; i < 32; i += 8)
        t[i][x] = W[(size_t)(bx + i) * NC + by + x];
    __syncthreads();
    for (int i = y; i < 32; i += 8)
        g_wt[(size_t)(by + i) * K + bx + x] = t[x][i];
}

// ---------------- tf32 mma.sync GEMM ----------------
// C[M,NC] = A[M,K_] @ W[K_,NC]; B = g_wt ([NC][K_] row-major == col-major B).
// BM=128, BN=64, BK=32; 8 warps (4m x 2n), warp tile 32x32 (2x4 m16n8k8 frags).
// MODE 0: plain. MODE 1: relu((c + bias) * g * rsqrt(1+eps) + be)
#define SPAD 36   // smem row stride (words): (36*gid + tig) % 32 all-distinct
template <int K_, int MODE>
__global__ __launch_bounds__(256) void k_gemm_mma(
    const float* __restrict__ A, float* __restrict__ C,
    int M, int NC,
    const float* __restrict__ bias, const float* __restrict__ bng,
    const float* __restrict__ bnb) {
    __shared__ uint32_t As[128 * SPAD];
    __shared__ uint32_t Bs[64 * SPAD];
    const int tid = threadIdx.x;
    const int wid = tid >> 5;
    const int lane = tid & 31;
    const int gid = lane >> 2;       // group id 0..7
    const int tig = lane & 3;        // thread-in-group 0..3
    const int warp_m = wid & 3;      // 0..3  (32-row slice)
    const int warp_n = wid >> 2;     // 0..1  (32-col slice)
    const int m0 = blockIdx.x * 128;
    const int n0 = blockIdx.y * 64;
    const int K4 = K_ >> 2;

    float acc[2][4][4];
    #pragma unroll
    for (int mi = 0; mi < 2; mi++)
        #pragma unroll
        for (int ni = 0; ni < 4; ni++)
            #pragma unroll
            for (int j = 0; j < 4; j++) acc[mi][ni][j] = 0.f;

    const float4* A4 = (const float4*)A;
    const float4* Wt4 = (const float4*)g_wt;

    #pragma unroll 1
    for (int kt = 0; kt < K_; kt += 32) {
        int kt4 = kt >> 2;
        // A tile: 128 rows x 8 float4
        #pragma unroll
        for (int l = 0; l < 4; l++) {
            int t = tid + l * 256;           // 0..1023
            int r = t >> 3, q = t & 7;
            int gm = m0 + r;
            float4 v = make_float4(0.f, 0.f, 0.f, 0.f);
            if (gm < M) v = A4[(size_t)gm * K4 + kt4 + q];
            uint32_t* d = &As[r * SPAD + q * 4];
            d[0] = f2tf32(v.x); d[1] = f2tf32(v.y);
            d[2] = f2tf32(v.z); d[3] = f2tf32(v.w);
        }
        // B tile: 64 rows x 8 float4
        #pragma unroll
        for (int l = 0; l < 2; l++) {
            int t = tid + l * 256;           // 0..511
            int r = t >> 3, q = t & 7;
            float4 v = Wt4[(size_t)(n0 + r) * K4 + kt4 + q];
            uint32_t* d = &Bs[r * SPAD + q * 4];
            d[0] = f2tf32(v.x); d[1] = f2tf32(v.y);
            d[2] = f2tf32(v.z); d[3] = f2tf32(v.w);
        }
        __syncthreads();

        #pragma unroll
        for (int k8 = 0; k8 < 32; k8 += 8) {
            uint32_t a[2][4], b[4][2];
            #pragma unroll
            for (int mi = 0; mi < 2; mi++) {
                int mlo = warp_m * 32 + mi * 16 + gid;
                a[mi][0] = As[mlo * SPAD + k8 + tig];
                a[mi][1] = As[(mlo + 8) * SPAD + k8 + tig];
                a[mi][2] = As[mlo * SPAD + k8 + tig + 4];
                a[mi][3] = As[(mlo + 8) * SPAD + k8 + tig + 4];
            }
            #pragma unroll
            for (int ni = 0; ni < 4; ni++) {
                int n = warp_n * 32 + ni * 8 + gid;
                b[ni][0] = Bs[n * SPAD + k8 + tig];
                b[ni][1] = Bs[n * SPAD + k8 + tig + 4];
            }
            #pragma unroll
            for (int mi = 0; mi < 2; mi++)
                #pragma unroll
                for (int ni = 0; ni < 4; ni++)
                    mma_tf32(acc[mi][ni], a[mi], b[ni]);
        }
        __syncthreads();
    }

    // ---- epilogue: fragment rows/cols -> global, fused bias/BN/ReLU
    const float inv = rsqrtf(1.0f + 1e-5f);
    #pragma unroll
    for (int ni = 0; ni < 4; ni++) {
        int gn = n0 + warp_n * 32 + ni * 8 + tig * 2;
        float bi0 = 0.f, bi1 = 0.f, sc0 = 0.f, sc1 = 0.f, bb0 = 0.f, bb1 = 0.f;
        if (MODE == 1) {
            bi0 = __ldg(&bias[gn]);     bi1 = __ldg(&bias[gn + 1]);
            sc0 = __ldg(&bng[gn]) * inv; sc1 = __ldg(&bng[gn + 1]) * inv;
            bb0 = __ldg(&bnb[gn]);      bb1 = __ldg(&bnb[gn + 1]);
        }
        #pragma unroll
        for (int mi = 0; mi < 2; mi++) {
            int r0 = m0 + warp_m * 32 + mi * 16 + gid;
            #pragma unroll
            for (int h = 0; h < 2; h++) {       // h=0: rows gid, h=1: rows gid+8
                int gm = r0 + h * 8;
                if (gm < M) {
                    float v0 = acc[mi][ni][h * 2 + 0];
                    float v1 = acc[mi][ni][h * 2 + 1];
                    if (MODE == 1) {
                        v0 = fmaxf(fmaf(v0 + bi0, sc0, bb0), 0.f);
                        v1 = fmaxf(fmaf(v1 + bi1, sc1, bb1), 0.f);
                    }
                    *(float2*)&C[(size_t)gm * NC + gn] = make_float2(v0, v1);
                }
            }
        }
    }
}

// ---------------- log_softmax over 128 cols, warp per row, +final bias
__global__ void k_logsoftmax(const float* __restrict__ in,
                             const float* __restrict__ bl,
                             float* __restrict__ out) {
    int gw = (blockIdx.x * blockDim.x + threadIdx.x) >> 5;
    int lane = threadIdx.x & 31;
    if (gw >= N_NODES) return;
    float4 v = ((const float4*)in)[gw * 32 + lane];
    float4 b = ((const float4*)bl)[lane];
    v.x += b.x; v.y += b.y; v.z += b.z; v.w += b.w;
    float m = fmaxf(fmaxf(v.x, v.y), fmaxf(v.z, v.w));
    #pragma unroll
    for (int o = 16; o; o >>= 1) m = fmaxf(m, __shfl_xor_sync(0xFFFFFFFFu, m, o));
    float s = expf(v.x - m) + expf(v.y - m) + expf(v.z - m) + expf(v.w - m);
    #pragma unroll
    for (int o = 16; o; o >>= 1) s += __shfl_xor_sync(0xFFFFFFFFu, s, o);
    float lse = m + logf(s);
    float4 o4;
    o4.x = v.x - lse; o4.y = v.y - lse; o4.z = v.z - lse; o4.w = v.w - lse;
    ((float4*)out)[gw * 32 + lane] = o4;
}

// ---------------- driver ----------------
extern "C" void kernel_launch(void* const* d_in, const int* in_sizes, int n_in,
                              void* d_out, int out_size) {
    const float* x   = (const float*)d_in[0];
    const void*  ei  = d_in[1];
    const float* ew  = (const float*)d_in[2];
    const float* W0  = (const float*)d_in[3];
    const float* b0  = (const float*)d_in[4];
    const float* W1  = (const float*)d_in[5];
    const float* b1  = (const float*)d_in[6];
    const float* Wl  = (const float*)d_in[7];
    const float* bl  = (const float*)d_in[8];
    const float* g0  = (const float*)d_in[9];
    const float* be0 = (const float*)d_in[10];
    const float* g1  = (const float*)d_in[11];
    const float* be1 = (const float*)d_in[12];
    float* out = (float*)d_out;

    float* bufA = nullptr;
    float* bufB = nullptr;
    cudaGetSymbolAddress((void**)&bufA, g_bufA);
    cudaGetSymbolAddress((void**)&bufB, g_bufB);

    const int NB_N = (N_NODES + 255) / 256;
    const int NB_E = (N_EDGES + 255) / 256;
    const int NB_W = (N_NODES * 32 + 255) / 256;
    const int MT   = (N_NODES + 127) / 128;      // 391 m-tiles

    // dtype probe + graph build
    k_detect<<<1, 1024>>>((const int*)ei);
    k_init<<<NB_N, 256>>>();
    k_degcount<<<NB_E, 256>>>(ei, ew);
    k_dinv<<<NB_N, 256>>>();
    k_scan1<<<SCAN_NB, SCAN_B>>>();
    k_scan2<<<1, 32>>>();
    k_scan3<<<NB_N, 256>>>();
    k_scatter<<<NB_E, 256>>>(ei, ew);

    // layer 0: agg(x)[N,128] -> bufA; tf32 GEMM 128->256 (+b0,BN0,ReLU) -> bufB
    k_agg<1><<<NB_W, 256>>>(x, bufA);
    k_transpose<<<dim3(DIM_IN / 32, DIM_HID / 32), dim3(32, 8)>>>(W0, DIM_IN, DIM_HID);
    k_gemm_mma<128, 1><<<dim3(MT, DIM_HID / 64), 256>>>(
        bufA, bufB, N_NODES, DIM_HID, b0, g0, be0);

    // layer 1: agg(bufB)[N,256] -> bufA; tf32 GEMM 256->256 (+b1,BN1,ReLU) -> bufB
    k_agg<2><<<NB_W, 256>>>(bufB, bufA);
    k_transpose<<<dim3(DIM_HID / 32, DIM_HID / 32), dim3(32, 8)>>>(W1, DIM_HID, DIM_HID);
    k_gemm_mma<256, 1><<<dim3(MT, DIM_HID / 64), 256>>>(
        bufA, bufB, N_NODES, DIM_HID, b1, g1, be1);

    // layer 2: tf32 GEMM 256->128 (plain) bufB->bufA; agg at dim 128 bufA->bufB
    k_transpose<<<dim3(DIM_HID / 32, DIM_OUT / 32), dim3(32, 8)>>>(Wl, DIM_HID, DIM_OUT);
    k_gemm_mma<256, 0><<<dim3(MT, DIM_OUT / 64), 256>>>(
        bufB, bufA, N_NODES, DIM_OUT, nullptr, nullptr, nullptr);
    k_agg<1><<<NB_W, 256>>>(bufA, bufB);

    // +bl and log_softmax
    k_logsoftmax<<<NB_W, 256>>>(bufB, bl, out);
}

// round 12
// speedup vs baseline: 1.9926x; 1.3449x over previous
#include <cuda_runtime.h>
#include <cstdint>

#define N_NODES 50000
#define N_EDGES 800000
#define DIM_IN  128
#define DIM_HID 256
#define DIM_OUT 128
#define SCAN_B  512
#define SCAN_NB 98   // ceil(50000/512)

// ---------------- scratch (no allocations allowed) ----------------
__device__ __align__(16) float g_bufA[N_NODES * DIM_HID];   // 51.2 MB (bf16 or fp32 views)
__device__ __align__(16) float g_bufB[N_NODES * DIM_HID];   // 51.2 MB
__device__ __align__(16) uint16_t g_wt16[DIM_HID * DIM_HID]; // transposed bf16 weights
__device__ float g_deg[N_NODES];
__device__ float g_dinv[N_NODES];
__device__ int   g_count[N_NODES];
__device__ int   g_indptr[N_NODES];
__device__ int   g_cursor[N_NODES];
__device__ int   g_blocksums[SCAN_NB];
__device__ int   g_esrc[N_EDGES];
__device__ float g_enorm[N_EDGES];
__device__ int   g_i64;          // 1 if edge_index is int64, 0 if int32

__device__ __forceinline__ int clampi(int v) {
    return min(max(v, 0), N_NODES - 1);
}
__device__ __forceinline__ int eidx(const void* ei, int j, int e) {
    if (g_i64) return clampi((int)((const long long*)ei)[j * N_EDGES + e]);
    return clampi(((const int*)ei)[j * N_EDGES + e]);
}

// bf16 helpers (bf16x2 packed in uint32: lo = lower address element)
__device__ __forceinline__ float bflo(uint32_t u) { return __uint_as_float(u << 16); }
__device__ __forceinline__ float bfhi(uint32_t u) { return __uint_as_float(u & 0xffff0000u); }
__device__ __forceinline__ uint32_t bfpack(float lo, float hi) {
    uint32_t r;
    asm("cvt.rn.bf16x2.f32 %0, %1, %2;" : "=r"(r) : "f"(hi), "f"(lo));
    return r;
}
__device__ __forceinline__ uint16_t bf1(float f) {
    uint16_t r;
    asm("cvt.rn.bf16.f32 %0, %1;" : "=h"(r) : "f"(f));
    return r;
}
__device__ __forceinline__ void mma_bf16(float* c, const uint32_t* a, const uint32_t* b) {
    asm volatile(
        "mma.sync.aligned.m16n8k16.row.col.f32.bf16.bf16.f32 "
        "{%0,%1,%2,%3}, {%4,%5,%6,%7}, {%8,%9}, {%0,%1,%2,%3};"
        : "+f"(c[0]), "+f"(c[1]), "+f"(c[2]), "+f"(c[3])
        : "r"(a[0]), "r"(a[1]), "r"(a[2]), "r"(a[3]), "r"(b[0]), "r"(b[1]));
}

// ---------------- dtype detection ----------------
__global__ void k_detect(const int* __restrict__ ei32) {
    __shared__ int s_nz;
    if (threadIdx.x == 0) s_nz = 0;
    __syncthreads();
    int nz = 0;
    for (int t = threadIdx.x; t < 2048; t += blockDim.x)
        if (ei32[2 * t + 1] != 0) nz = 1;
    if (nz) atomicOr(&s_nz, 1);
    __syncthreads();
    if (threadIdx.x == 0) g_i64 = (s_nz == 0) ? 1 : 0;
}

// ---------------- graph build ----------------
__global__ void k_init() {
    int i = blockIdx.x * blockDim.x + threadIdx.x;
    if (i < N_NODES) { g_deg[i] = 1.0f; g_count[i] = 0; }
}

__global__ void k_degcount(const void* __restrict__ ei,
                           const float* __restrict__ ew) {
    int e = blockIdx.x * blockDim.x + threadIdx.x;
    if (e < N_EDGES) {
        int c = eidx(ei, 1, e);
        atomicAdd(&g_deg[c], ew[e]);
        atomicAdd(&g_count[c], 1);
    }
}

__global__ void k_dinv() {
    int i = blockIdx.x * blockDim.x + threadIdx.x;
    if (i < N_NODES) g_dinv[i] = rsqrtf(g_deg[i]);
}

__global__ void k_scan1() {
    __shared__ int sh[SCAN_B];
    int tid = threadIdx.x;
    int i = blockIdx.x * SCAN_B + tid;
    int v = (i < N_NODES) ? g_count[i] : 0;
    sh[tid] = v;
    __syncthreads();
    #pragma unroll
    for (int off = 1; off < SCAN_B; off <<= 1) {
        int t = (tid >= off) ? sh[tid - off] : 0;
        __syncthreads();
        sh[tid] += t;
        __syncthreads();
    }
    if (i < N_NODES) g_indptr[i] = sh[tid] - v;
    if (tid == SCAN_B - 1) g_blocksums[blockIdx.x] = sh[SCAN_B - 1];
}

__global__ void k_scan2() {
    if (threadIdx.x == 0) {
        int s = 0;
        for (int b = 0; b < SCAN_NB; b++) {
            int t = g_blocksums[b];
            g_blocksums[b] = s;
            s += t;
        }
    }
}

__global__ void k_scan3() {
    int i = blockIdx.x * blockDim.x + threadIdx.x;
    if (i < N_NODES) {
        int p = g_indptr[i] + g_blocksums[i >> 9];
        g_indptr[i] = p;
        g_cursor[i] = p;
    }
}

__global__ void k_scatter(const void* __restrict__ ei,
                          const float* __restrict__ ew) {
    int e = blockIdx.x * blockDim.x + threadIdx.x;
    if (e < N_EDGES) {
        int r = eidx(ei, 0, e);
        int c = eidx(ei, 1, e);
        int pos = atomicAdd(&g_cursor[c], 1);
        g_esrc[pos] = r;
        g_enorm[pos] = g_dinv[r] * ew[e] * g_dinv[c];
    }
}

// ---------------- x fp32 -> bf16 convert ----------------
__global__ void k_cvt(const float* __restrict__ x, uint32_t* __restrict__ xb) {
    int i = blockIdx.x * blockDim.x + threadIdx.x;   // word index
    if (i < N_NODES * (DIM_IN / 2)) {
        float2 v = ((const float2*)x)[i];
        xb[i] = bfpack(v.x, v.y);
    }
}

// ---------------- bf16 aggregation (warp per node, W words per lane) ----------------
// out[n] = dinv[n]^2*src[n] + sum_e norm*src[src_e];  dim = W*64 bf16
template <int W>
__global__ void k_agg_bf(const uint32_t* __restrict__ src, uint32_t* __restrict__ dst) {
    int gw = (blockIdx.x * blockDim.x + threadIdx.x) >> 5;
    int lane = threadIdx.x & 31;
    if (gw >= N_NODES) return;
    const int rs = W * 32;                     // words per row
    float dn = g_dinv[gw], sw = dn * dn;
    uint32_t u[W];
    {
        const uint32_t* p = src + (size_t)gw * rs + lane * W;
        if (W == 4) *(uint4*)u = *(const uint4*)p; else *(uint2*)u = *(const uint2*)p;
    }
    float acc[2 * W];
    #pragma unroll
    for (int w = 0; w < W; w++) {
        acc[2 * w]     = sw * bflo(u[w]);
        acc[2 * w + 1] = sw * bfhi(u[w]);
    }
    int i = g_indptr[gw];
    int end = i + g_count[gw];
    for (; i + 2 <= end; i += 2) {
        int r0 = g_esrc[i], r1 = g_esrc[i + 1];
        float w0 = g_enorm[i], w1 = g_enorm[i + 1];
        uint32_t u0[W], u1[W];
        const uint32_t* p0 = src + (size_t)r0 * rs + lane * W;
        const uint32_t* p1 = src + (size_t)r1 * rs + lane * W;
        if (W == 4) { *(uint4*)u0 = *(const uint4*)p0; *(uint4*)u1 = *(const uint4*)p1; }
        else        { *(uint2*)u0 = *(const uint2*)p0; *(uint2*)u1 = *(const uint2*)p1; }
        #pragma unroll
        for (int w = 0; w < W; w++) {
            acc[2 * w]     += w0 * bflo(u0[w]) + w1 * bflo(u1[w]);
            acc[2 * w + 1] += w0 * bfhi(u0[w]) + w1 * bfhi(u1[w]);
        }
    }
    if (i < end) {
        int r0 = g_esrc[i];
        float w0 = g_enorm[i];
        uint32_t u0[W];
        const uint32_t* p0 = src + (size_t)r0 * rs + lane * W;
        if (W == 4) *(uint4*)u0 = *(const uint4*)p0; else *(uint2*)u0 = *(const uint2*)p0;
        #pragma unroll
        for (int w = 0; w < W; w++) {
            acc[2 * w]     += w0 * bflo(u0[w]);
            acc[2 * w + 1] += w0 * bfhi(u0[w]);
        }
    }
    uint32_t o[W];
    #pragma unroll
    for (int w = 0; w < W; w++) o[w] = bfpack(acc[2 * w], acc[2 * w + 1]);
    uint32_t* q = dst + (size_t)gw * rs + lane * W;
    if (W == 4) *(uint4*)q = *(const uint4*)o; else *(uint2*)q = *(const uint2*)o;
}

// ---------------- fp32 aggregation (final layer), dim 128 ----------------
__global__ void k_agg_f32(const float* __restrict__ src, float* __restrict__ dst) {
    int gw = (blockIdx.x * blockDim.x + threadIdx.x) >> 5;
    int lane = threadIdx.x & 31;
    if (gw >= N_NODES) return;
    const float4* s4 = (const float4*)src;
    float dn = g_dinv[gw], sw = dn * dn;
    float4 t = s4[gw * 32 + lane];
    float4 acc = make_float4(sw * t.x, sw * t.y, sw * t.z, sw * t.w);
    int i = g_indptr[gw];
    int end = i + g_count[gw];
    for (; i + 2 <= end; i += 2) {
        int r0 = g_esrc[i], r1 = g_esrc[i + 1];
        float w0 = g_enorm[i], w1 = g_enorm[i + 1];
        float4 t0 = s4[r0 * 32 + lane];
        float4 t1 = s4[r1 * 32 + lane];
        acc.x += w0 * t0.x + w1 * t1.x;
        acc.y += w0 * t0.y + w1 * t1.y;
        acc.z += w0 * t0.z + w1 * t1.z;
        acc.w += w0 * t0.w + w1 * t1.w;
    }
    if (i < end) {
        int r0 = g_esrc[i];
        float w0 = g_enorm[i];
        float4 t0 = s4[r0 * 32 + lane];
        acc.x += w0 * t0.x; acc.y += w0 * t0.y;
        acc.z += w0 * t0.z; acc.w += w0 * t0.w;
    }
    ((float4*)dst)[gw * 32 + lane] = acc;
}

// ---------------- weight transpose + bf16: Wt16[NC][K] = bf16(W[K][NC]) ----------------
__global__ void k_transpose(const float* __restrict__ W, int K, int NC) {
    __shared__ float t[32][33];
    int bx = blockIdx.x * 32;   // k block
    int by = blockIdx.y * 32;   // n block
    int x = threadIdx.x, y = threadIdx.y;
    for (int i = y; i < 32; i += 8)
        t[i][x] = W[(size_t)(bx + i) * NC + by + x];
    __syncthreads();
    for (int i = y; i < 32; i += 8)
        g_wt16[(size_t)(by + i) * K + bx + x] = bf1(t[x][i]);
}

// ---------------- bf16 mma.sync GEMM ----------------
// C[M,NC] = A[M,K_] @ W[K_,NC]; A bf16 words [M][K_/2]; B = g_wt16 [NC][K_].
// BM=128, BN=64, BK=64 bf16 (32 words); 8 warps (4m x 2n), warp tile 32x32.
// MODE 1: relu((c+bias)*g*rsqrt(1+eps)+be);  OUTBF: bf16-packed output.
#define SPAD 36   // smem row stride (words): (36*gid + 8g + tig) % 32 all-distinct
template <int K_, int MODE, int OUTBF>
__global__ __launch_bounds__(256) void k_gemm_bf(
    const uint32_t* __restrict__ A, void* __restrict__ C,
    int M, int NC,
    const float* __restrict__ bias, const float* __restrict__ bng,
    const float* __restrict__ bnb) {
    __shared__ uint32_t As[128 * SPAD];
    __shared__ uint32_t Bs[64 * SPAD];
    const int tid = threadIdx.x;
    const int wid = tid >> 5;
    const int lane = tid & 31;
    const int gid = lane >> 2;
    const int tig = lane & 3;
    const int warp_m = wid & 3;
    const int warp_n = wid >> 2;
    const int m0 = blockIdx.x * 128;
    const int n0 = blockIdx.y * 64;
    const int KW = K_ >> 1;                    // words per feature row
    const uint32_t* Bw = (const uint32_t*)g_wt16;

    float acc[2][4][4];
    #pragma unroll
    for (int mi = 0; mi < 2; mi++)
        #pragma unroll
        for (int ni = 0; ni < 4; ni++)
            #pragma unroll
            for (int j = 0; j < 4; j++) acc[mi][ni][j] = 0.f;

    #pragma unroll 1
    for (int kt = 0; kt < KW; kt += 32) {      // 32 words = 64 bf16 per BK tile
        // A tile: 128 rows x 8 uint4
        #pragma unroll
        for (int l = 0; l < 4; l++) {
            int t = tid + l * 256;             // 0..1023
            int r = t >> 3, q = t & 7;
            int gm = m0 + r;
            uint4 v = make_uint4(0u, 0u, 0u, 0u);
            if (gm < M) v = *(const uint4*)&A[(size_t)gm * KW + kt + q * 4];
            *(uint4*)&As[r * SPAD + q * 4] = v;
        }
        // B tile: 64 rows x 8 uint4
        #pragma unroll
        for (int l = 0; l < 2; l++) {
            int t = tid + l * 256;             // 0..511
            int r = t >> 3, q = t & 7;
            uint4 v = *(const uint4*)&Bw[(size_t)(n0 + r) * KW + kt + q * 4];
            *(uint4*)&Bs[r * SPAD + q * 4] = v;
        }
        __syncthreads();

        #pragma unroll
        for (int g8 = 0; g8 < 32; g8 += 8) {   // one k16 group per iter
            uint32_t a[2][4], b[4][2];
            #pragma unroll
            for (int mi = 0; mi < 2; mi++) {
                int mlo = warp_m * 32 + mi * 16 + gid;
                a[mi][0] = As[mlo * SPAD + g8 + tig];
                a[mi][1] = As[(mlo + 8) * SPAD + g8 + tig];
                a[mi][2] = As[mlo * SPAD + g8 + tig + 4];
                a[mi][3] = As[(mlo + 8) * SPAD + g8 + tig + 4];
            }
            #pragma unroll
            for (int ni = 0; ni < 4; ni++) {
                int n = warp_n * 32 + ni * 8 + gid;
                b[ni][0] = Bs[n * SPAD + g8 + tig];
                b[ni][1] = Bs[n * SPAD + g8 + tig + 4];
            }
            #pragma unroll
            for (int mi = 0; mi < 2; mi++)
                #pragma unroll
                for (int ni = 0; ni < 4; ni++)
                    mma_bf16(acc[mi][ni], a[mi], b[ni]);
        }
        __syncthreads();
    }

    // ---- epilogue
    const float inv = rsqrtf(1.0f + 1e-5f);
    #pragma unroll
    for (int ni = 0; ni < 4; ni++) {
        int gn = n0 + warp_n * 32 + ni * 8 + tig * 2;
        float bi0 = 0.f, bi1 = 0.f, sc0 = 0.f, sc1 = 0.f, bb0 = 0.f, bb1 = 0.f;
        if (MODE == 1) {
            bi0 = __ldg(&bias[gn]);      bi1 = __ldg(&bias[gn + 1]);
            sc0 = __ldg(&bng[gn]) * inv; sc1 = __ldg(&bng[gn + 1]) * inv;
            bb0 = __ldg(&bnb[gn]);       bb1 = __ldg(&bnb[gn + 1]);
        }
        #pragma unroll
        for (int mi = 0; mi < 2; mi++) {
            int r0 = m0 + warp_m * 32 + mi * 16 + gid;
            #pragma unroll
            for (int h = 0; h < 2; h++) {
                int gm = r0 + h * 8;
                if (gm < M) {
                    float v0 = acc[mi][ni][h * 2 + 0];
                    float v1 = acc[mi][ni][h * 2 + 1];
                    if (MODE == 1) {
                        v0 = fmaxf(fmaf(v0 + bi0, sc0, bb0), 0.f);
                        v1 = fmaxf(fmaf(v1 + bi1, sc1, bb1), 0.f);
                    }
                    if (OUTBF) {
                        ((uint32_t*)C)[(size_t)gm * (NC >> 1) + (gn >> 1)] = bfpack(v0, v1);
                    } else {
                        *(float2*)&((float*)C)[(size_t)gm * NC + gn] = make_float2(v0, v1);
                    }
                }
            }
        }
    }
}

// ---------------- log_softmax over 128 cols, warp per row, +final bias
__global__ void k_logsoftmax(const float* __restrict__ in,
                             const float* __restrict__ bl,
                             float* __restrict__ out) {
    int gw = (blockIdx.x * blockDim.x + threadIdx.x) >> 5;
    int lane = threadIdx.x & 31;
    if (gw >= N_NODES) return;
    float4 v = ((const float4*)in)[gw * 32 + lane];
    float4 b = ((const float4*)bl)[lane];
    v.x += b.x; v.y += b.y; v.z += b.z; v.w += b.w;
    float m = fmaxf(fmaxf(v.x, v.y), fmaxf(v.z, v.w));
    #pragma unroll
    for (int o = 16; o; o >>= 1) m = fmaxf(m, __shfl_xor_sync(0xFFFFFFFFu, m, o));
    float s = expf(v.x - m) + expf(v.y - m) + expf(v.z - m) + expf(v.w - m);
    #pragma unroll
    for (int o = 16; o; o >>= 1) s += __shfl_xor_sync(0xFFFFFFFFu, s, o);
    float lse = m + logf(s);
    float4 o4;
    o4.x = v.x - lse; o4.y = v.y - lse; o4.z = v.z - lse; o4.w = v.w - lse;
    ((float4*)out)[gw * 32 + lane] = o4;
}

// ---------------- driver ----------------
extern "C" void kernel_launch(void* const* d_in, const int* in_sizes, int n_in,
                              void* d_out, int out_size) {
    const float* x   = (const float*)d_in[0];
    const void*  ei  = d_in[1];
    const float* ew  = (const float*)d_in[2];
    const float* W0  = (const float*)d_in[3];
    const float* b0  = (const float*)d_in[4];
    const float* W1  = (const float*)d_in[5];
    const float* b1  = (const float*)d_in[6];
    const float* Wl  = (const float*)d_in[7];
    const float* bl  = (const float*)d_in[8];
    const float* g0  = (const float*)d_in[9];
    const float* be0 = (const float*)d_in[10];
    const float* g1  = (const float*)d_in[11];
    const float* be1 = (const float*)d_in[12];
    float* out = (float*)d_out;

    float* bufA = nullptr;
    float* bufB = nullptr;
    cudaGetSymbolAddress((void**)&bufA, g_bufA);
    cudaGetSymbolAddress((void**)&bufB, g_bufB);
    uint32_t* wA = (uint32_t*)bufA;
    uint32_t* wB = (uint32_t*)bufB;

    const int NB_N = (N_NODES + 255) / 256;
    const int NB_E = (N_EDGES + 255) / 256;
    const int NB_W = (N_NODES * 32 + 255) / 256;
    const int MT   = (N_NODES + 127) / 128;      // 391 m-tiles

    // dtype probe + graph build
    k_detect<<<1, 1024>>>((const int*)ei);
    k_init<<<NB_N, 256>>>();
    k_degcount<<<NB_E, 256>>>(ei, ew);
    k_dinv<<<NB_N, 256>>>();
    k_scan1<<<SCAN_NB, SCAN_B>>>();
    k_scan2<<<1, 32>>>();
    k_scan3<<<NB_N, 256>>>();
    k_scatter<<<NB_E, 256>>>(ei, ew);

    // x -> bf16 (into bufB region)
    k_cvt<<<(N_NODES * 64 + 255) / 256, 256>>>(x, wB);

    // layer 0: agg_bf(x_bf)[N,128] -> wA; bf16 GEMM 128->256 (+b0,BN0,ReLU) -> wB
    k_agg_bf<2><<<NB_W, 256>>>(wB, wA);
    k_transpose<<<dim3(DIM_IN / 32, DIM_HID / 32), dim3(32, 8)>>>(W0, DIM_IN, DIM_HID);
    k_gemm_bf<128, 1, 1><<<dim3(MT, DIM_HID / 64), 256>>>(
        wA, wB, N_NODES, DIM_HID, b0, g0, be0);

    // layer 1: agg_bf[N,256] wB -> wA; bf16 GEMM 256->256 (+b1,BN1,ReLU) -> wB
    k_agg_bf<4><<<NB_W, 256>>>(wB, wA);
    k_transpose<<<dim3(DIM_HID / 32, DIM_HID / 32), dim3(32, 8)>>>(W1, DIM_HID, DIM_HID);
    k_gemm_bf<256, 1, 1><<<dim3(MT, DIM_HID / 64), 256>>>(
        wA, wB, N_NODES, DIM_HID, b1, g1, be1);

    // layer 2: bf16 GEMM 256->128 (plain, fp32 out) wB -> bufA; fp32 agg -> bufB
    k_transpose<<<dim3(DIM_HID / 32, DIM_OUT / 32), dim3(32, 8)>>>(Wl, DIM_HID, DIM_OUT);
    k_gemm_bf<256, 0, 0><<<dim3(MT, DIM_OUT / 64), 256>>>(
        wB, bufA, N_NODES, DIM_OUT, nullptr, nullptr, nullptr);
    k_agg_f32<<<NB_W, 256>>>(bufA, bufB);

    // +bl and log_softmax
    k_logsoftmax<<<NB_W, 256>>>(bufB, bl, out);
}

// round 13
// speedup vs baseline: 2.2304x; 1.1193x over previous
#include <cuda_runtime.h>
#include <cuda_fp16.h>
#include <cstdint>

#define N_NODES 50000
#define N_EDGES 800000
#define DIM_IN  128
#define DIM_HID 256
#define DIM_OUT 128
#define SCAN_B  512
#define SCAN_NB 98   // ceil(50000/512)

// ---------------- scratch (no allocations allowed) ----------------
__device__ __align__(16) float g_bufA[N_NODES * DIM_HID];   // 51.2 MB
__device__ __align__(16) float g_bufB[N_NODES * DIM_HID];   // 51.2 MB
__device__ __align__(16) uint16_t g_wt0[DIM_IN  * DIM_HID];
__device__ __align__(16) uint16_t g_wt1[DIM_HID * DIM_HID];
__device__ __align__(16) uint16_t g_wt2[DIM_HID * DIM_OUT];
__device__ float g_deg[N_NODES];
__device__ float g_dinv[N_NODES];
__device__ int   g_count[N_NODES];
__device__ int   g_indptr[N_NODES];
__device__ int   g_cursor[N_NODES];
__device__ int   g_blocksums[SCAN_NB];
__device__ int   g_esrc[N_EDGES];
__device__ float g_enorm[N_EDGES];
__device__ int   g_i64;

__device__ __forceinline__ int clampi(int v) {
    return min(max(v, 0), N_NODES - 1);
}
__device__ __forceinline__ int eidx(const void* ei, int j, int e) {
    if (g_i64) return clampi((int)((const long long*)ei)[j * N_EDGES + e]);
    return clampi(((const int*)ei)[j * N_EDGES + e]);
}

// bf16 helpers (bf16x2 packed in uint32: lo = lower address element)
__device__ __forceinline__ float bflo(uint32_t u) { return __uint_as_float(u << 16); }
__device__ __forceinline__ float bfhi(uint32_t u) { return __uint_as_float(u & 0xffff0000u); }
__device__ __forceinline__ uint32_t bfpack(float lo, float hi) {
    uint32_t r;
    asm("cvt.rn.bf16x2.f32 %0, %1, %2;" : "=r"(r) : "f"(hi), "f"(lo));
    return r;
}
__device__ __forceinline__ uint16_t bf1(float f) {
    uint16_t r;
    asm("cvt.rn.bf16.f32 %0, %1;" : "=h"(r) : "f"(f));
    return r;
}
// fp16 pack (f16x2): lo = lower address element
__device__ __forceinline__ uint32_t hfpack(float lo, float hi) {
    uint32_t r;
    asm("cvt.rn.f16x2.f32 %0, %1, %2;" : "=r"(r) : "f"(hi), "f"(lo));
    return r;
}
__device__ __forceinline__ void mma_bf16(float* c, const uint32_t* a, const uint32_t* b) {
    asm volatile(
        "mma.sync.aligned.m16n8k16.row.col.f32.bf16.bf16.f32 "
        "{%0,%1,%2,%3}, {%4,%5,%6,%7}, {%8,%9}, {%0,%1,%2,%3};"
        : "+f"(c[0]), "+f"(c[1]), "+f"(c[2]), "+f"(c[3])
        : "r"(a[0]), "r"(a[1]), "r"(a[2]), "r"(a[3]), "r"(b[0]), "r"(b[1]));
}

// ---------------- fused: dtype detect (block 0) + init (blocks<196) + x->bf16 ----------------
#define NB_INIT 196                       // ceil(50000/256)
#define NB_CVT  12500                     // 50000*64/256 words
__global__ void k_pre(const int* __restrict__ ei32,
                      const float* __restrict__ x, uint32_t* __restrict__ xb) {
    int bid = blockIdx.x;
    if (bid == 0) {                       // detect (256 threads, 2048 words)
        __shared__ int s_nz;
        if (threadIdx.x == 0) s_nz = 0;
        __syncthreads();
        int nz = 0;
        for (int t = threadIdx.x; t < 2048; t += blockDim.x)
            if (ei32[2 * t + 1] != 0) nz = 1;
        if (nz) atomicOr(&s_nz, 1);
        __syncthreads();
        if (threadIdx.x == 0) g_i64 = (s_nz == 0) ? 1 : 0;
    }
    if (bid < NB_INIT) {
        int i = bid * 256 + threadIdx.x;
        if (i < N_NODES) { g_deg[i] = 1.0f; g_count[i] = 0; }
    } else {
        int i = (bid - NB_INIT) * 256 + threadIdx.x;   // word index
        if (i < N_NODES * (DIM_IN / 2)) {
            float2 v = ((const float2*)x)[i];
            xb[i] = bfpack(v.x, v.y);
        }
    }
}

// ---------------- graph build ----------------
__global__ void k_degcount(const void* __restrict__ ei,
                           const float* __restrict__ ew) {
    int e = blockIdx.x * blockDim.x + threadIdx.x;
    if (e < N_EDGES) {
        int c = eidx(ei, 1, e);
        atomicAdd(&g_deg[c], ew[e]);
        atomicAdd(&g_count[c], 1);
    }
}

__global__ void k_scan1() {
    __shared__ int sh[SCAN_B];
    int tid = threadIdx.x;
    int i = blockIdx.x * SCAN_B + tid;
    int v = (i < N_NODES) ? g_count[i] : 0;
    sh[tid] = v;
    __syncthreads();
    #pragma unroll
    for (int off = 1; off < SCAN_B; off <<= 1) {
        int t = (tid >= off) ? sh[tid - off] : 0;
        __syncthreads();
        sh[tid] += t;
        __syncthreads();
    }
    if (i < N_NODES) g_indptr[i] = sh[tid] - v;
    if (tid == SCAN_B - 1) g_blocksums[blockIdx.x] = sh[SCAN_B - 1];
}

__global__ void k_scan2() {
    if (threadIdx.x == 0) {
        int s = 0;
        for (int b = 0; b < SCAN_NB; b++) {
            int t = g_blocksums[b];
            g_blocksums[b] = s;
            s += t;
        }
    }
}

__global__ void k_scan3() {      // + dinv fused
    int i = blockIdx.x * blockDim.x + threadIdx.x;
    if (i < N_NODES) {
        int p = g_indptr[i] + g_blocksums[i >> 9];
        g_indptr[i] = p;
        g_cursor[i] = p;
        g_dinv[i] = rsqrtf(g_deg[i]);
    }
}

__global__ void k_scatter(const void* __restrict__ ei,
                          const float* __restrict__ ew) {
    int e = blockIdx.x * blockDim.x + threadIdx.x;
    if (e < N_EDGES) {
        int r = eidx(ei, 0, e);
        int c = eidx(ei, 1, e);
        int pos = atomicAdd(&g_cursor[c], 1);
        g_esrc[pos] = r;
        g_enorm[pos] = g_dinv[r] * ew[e] * g_dinv[c];
    }
}

// ---------------- bf16 aggregation (warp per node, W words per lane) ----------------
template <int W>
__global__ void k_agg_bf(const uint32_t* __restrict__ src, uint32_t* __restrict__ dst) {
    int gw = (blockIdx.x * blockDim.x + threadIdx.x) >> 5;
    int lane = threadIdx.x & 31;
    if (gw >= N_NODES) return;
    const int rs = W * 32;
    float dn = g_dinv[gw], sw = dn * dn;
    uint32_t u[W];
    {
        const uint32_t* p = src + (size_t)gw * rs + lane * W;
        if (W == 4) *(uint4*)u = *(const uint4*)p; else *(uint2*)u = *(const uint2*)p;
    }
    float acc[2 * W];
    #pragma unroll
    for (int w = 0; w < W; w++) {
        acc[2 * w]     = sw * bflo(u[w]);
        acc[2 * w + 1] = sw * bfhi(u[w]);
    }
    int i = g_indptr[gw];
    int end = i + g_count[gw];
    for (; i + 2 <= end; i += 2) {
        int r0 = g_esrc[i], r1 = g_esrc[i + 1];
        float w0 = g_enorm[i], w1 = g_enorm[i + 1];
        uint32_t u0[W], u1[W];
        const uint32_t* p0 = src + (size_t)r0 * rs + lane * W;
        const uint32_t* p1 = src + (size_t)r1 * rs + lane * W;
        if (W == 4) { *(uint4*)u0 = *(const uint4*)p0; *(uint4*)u1 = *(const uint4*)p1; }
        else        { *(uint2*)u0 = *(const uint2*)p0; *(uint2*)u1 = *(const uint2*)p1; }
        #pragma unroll
        for (int w = 0; w < W; w++) {
            acc[2 * w]     += w0 * bflo(u0[w]) + w1 * bflo(u1[w]);
            acc[2 * w + 1] += w0 * bfhi(u0[w]) + w1 * bfhi(u1[w]);
        }
    }
    if (i < end) {
        int r0 = g_esrc[i];
        float w0 = g_enorm[i];
        uint32_t u0[W];
        const uint32_t* p0 = src + (size_t)r0 * rs + lane * W;
        if (W == 4) *(uint4*)u0 = *(const uint4*)p0; else *(uint2*)u0 = *(const uint2*)p0;
        #pragma unroll
        for (int w = 0; w < W; w++) {
            acc[2 * w]     += w0 * bflo(u0[w]);
            acc[2 * w + 1] += w0 * bfhi(u0[w]);
        }
    }
    uint32_t o[W];
    #pragma unroll
    for (int w = 0; w < W; w++) o[w] = bfpack(acc[2 * w], acc[2 * w + 1]);
    uint32_t* q = dst + (size_t)gw * rs + lane * W;
    if (W == 4) *(uint4*)q = *(const uint4*)o; else *(uint2*)q = *(const uint2*)o;
}

// ---------------- fused final: fp16 agg (dim 128) + bias + log_softmax ----------------
__global__ void k_agg_softmax(const uint32_t* __restrict__ src,
                              const float* __restrict__ bl,
                              float* __restrict__ out) {
    int gw = (blockIdx.x * blockDim.x + threadIdx.x) >> 5;
    int lane = threadIdx.x & 31;
    if (gw >= N_NODES) return;
    const int rs = 64;                           // fp16 words per row (128 vals)
    float dn = g_dinv[gw], sw = dn * dn;
    float acc[4];
    {
        uint2 u = *(const uint2*)(src + (size_t)gw * rs + lane * 2);
        float2 a = __half22float2(*(__half2*)&u.x);
        float2 b = __half22float2(*(__half2*)&u.y);
        acc[0] = sw * a.x; acc[1] = sw * a.y; acc[2] = sw * b.x; acc[3] = sw * b.y;
    }
    int i = g_indptr[gw];
    int end = i + g_count[gw];
    for (; i + 2 <= end; i += 2) {
        int r0 = g_esrc[i], r1 = g_esrc[i + 1];
        float w0 = g_enorm[i], w1 = g_enorm[i + 1];
        uint2 u0 = *(const uint2*)(src + (size_t)r0 * rs + lane * 2);
        uint2 u1 = *(const uint2*)(src + (size_t)r1 * rs + lane * 2);
        float2 a0 = __half22float2(*(__half2*)&u0.x);
        float2 b0 = __half22float2(*(__half2*)&u0.y);
        float2 a1 = __half22float2(*(__half2*)&u1.x);
        float2 b1 = __half22float2(*(__half2*)&u1.y);
        acc[0] += w0 * a0.x + w1 * a1.x;
        acc[1] += w0 * a0.y + w1 * a1.y;
        acc[2] += w0 * b0.x + w1 * b1.x;
        acc[3] += w0 * b0.y + w1 * b1.y;
    }
    if (i < end) {
        int r0 = g_esrc[i];
        float w0 = g_enorm[i];
        uint2 u0 = *(const uint2*)(src + (size_t)r0 * rs + lane * 2);
        float2 a0 = __half22float2(*(__half2*)&u0.x);
        float2 b0 = __half22float2(*(__half2*)&u0.y);
        acc[0] += w0 * a0.x; acc[1] += w0 * a0.y;
        acc[2] += w0 * b0.x; acc[3] += w0 * b0.y;
    }
    float4 b = ((const float4*)bl)[lane];
    acc[0] += b.x; acc[1] += b.y; acc[2] += b.z; acc[3] += b.w;
    float m = fmaxf(fmaxf(acc[0], acc[1]), fmaxf(acc[2], acc[3]));
    #pragma unroll
    for (int o = 16; o; o >>= 1) m = fmaxf(m, __shfl_xor_sync(0xFFFFFFFFu, m, o));
    float s = expf(acc[0] - m) + expf(acc[1] - m) + expf(acc[2] - m) + expf(acc[3] - m);
    #pragma unroll
    for (int o = 16; o; o >>= 1) s += __shfl_xor_sync(0xFFFFFFFFu, s, o);
    float lse = m + logf(s);
    float4 o4 = make_float4(acc[0] - lse, acc[1] - lse, acc[2] - lse, acc[3] - lse);
    ((float4*)out)[gw * 32 + lane] = o4;
}

// ---------------- fused weight transposes: Wt[NC][K] = bf16(W[K][NC]) ----------------
// 128 tiles of 32x32: W0 tiles [0,32), W1 [32,96), Wl [96,128)
__global__ void k_transpose_all(const float* __restrict__ W0,
                                const float* __restrict__ W1,
                                const float* __restrict__ Wl) {
    __shared__ float t[32][33];
    int bid = blockIdx.x;
    const float* W; uint16_t* D; int K, NC, tk, tn;
    if (bid < 32)      { W = W0; D = g_wt0; K = DIM_IN;  NC = DIM_HID; int b = bid;      tk = b & 3; tn = b >> 2; }
    else if (bid < 96) { W = W1; D = g_wt1; K = DIM_HID; NC = DIM_HID; int b = bid - 32; tk = b & 7; tn = b >> 3; }
    else               { W = Wl; D = g_wt2; K = DIM_HID; NC = DIM_OUT; int b = bid - 96; tk = b & 7; tn = b >> 3; }
    int bx = tk * 32, by = tn * 32;
    int x = threadIdx.x, y = threadIdx.y;
    for (int i = y; i < 32; i += 8)
        t[i][x] = W[(size_t)(bx + i) * NC + by + x];
    __syncthreads();
    for (int i = y; i < 32; i += 8)
        D[(size_t)(by + i) * K + bx + x] = bf1(t[x][i]);
}

// ---------------- bf16 mma.sync GEMM ----------------
// OUT: 0 = fp32, 1 = bf16-packed, 2 = fp16-packed
#define SPAD 36
template <int K_, int MODE, int OUT>
__global__ __launch_bounds__(256) void k_gemm_bf(
    const uint32_t* __restrict__ A, const uint16_t* __restrict__ Bw16,
    void* __restrict__ C, int M, int NC,
    const float* __restrict__ bias, const float* __restrict__ bng,
    const float* __restrict__ bnb) {
    __shared__ uint32_t As[128 * SPAD];
    __shared__ uint32_t Bs[64 * SPAD];
    const int tid = threadIdx.x;
    const int wid = tid >> 5;
    const int lane = tid & 31;
    const int gid = lane >> 2;
    const int tig = lane & 3;
    const int warp_m = wid & 3;
    const int warp_n = wid >> 2;
    const int m0 = blockIdx.x * 128;
    const int n0 = blockIdx.y * 64;
    const int KW = K_ >> 1;
    const uint32_t* Bw = (const uint32_t*)Bw16;

    float acc[2][4][4];
    #pragma unroll
    for (int mi = 0; mi < 2; mi++)
        #pragma unroll
        for (int ni = 0; ni < 4; ni++)
            #pragma unroll
            for (int j = 0; j < 4; j++) acc[mi][ni][j] = 0.f;

    #pragma unroll 1
    for (int kt = 0; kt < KW; kt += 32) {
        #pragma unroll
        for (int l = 0; l < 4; l++) {
            int t = tid + l * 256;
            int r = t >> 3, q = t & 7;
            int gm = m0 + r;
            uint4 v = make_uint4(0u, 0u, 0u, 0u);
            if (gm < M) v = *(const uint4*)&A[(size_t)gm * KW + kt + q * 4];
            *(uint4*)&As[r * SPAD + q * 4] = v;
        }
        #pragma unroll
        for (int l = 0; l < 2; l++) {
            int t = tid + l * 256;
            int r = t >> 3, q = t & 7;
            uint4 v = *(const uint4*)&Bw[(size_t)(n0 + r) * KW + kt + q * 4];
            *(uint4*)&Bs[r * SPAD + q * 4] = v;
        }
        __syncthreads();

        #pragma unroll
        for (int g8 = 0; g8 < 32; g8 += 8) {
            uint32_t a[2][4], b[4][2];
            #pragma unroll
            for (int mi = 0; mi < 2; mi++) {
                int mlo = warp_m * 32 + mi * 16 + gid;
                a[mi][0] = As[mlo * SPAD + g8 + tig];
                a[mi][1] = As[(mlo + 8) * SPAD + g8 + tig];
                a[mi][2] = As[mlo * SPAD + g8 + tig + 4];
                a[mi][3] = As[(mlo + 8) * SPAD + g8 + tig + 4];
            }
            #pragma unroll
            for (int ni = 0; ni < 4; ni++) {
                int n = warp_n * 32 + ni * 8 + gid;
                b[ni][0] = Bs[n * SPAD + g8 + tig];
                b[ni][1] = Bs[n * SPAD + g8 + tig + 4];
            }
            #pragma unroll
            for (int mi = 0; mi < 2; mi++)
                #pragma unroll
                for (int ni = 0; ni < 4; ni++)
                    mma_bf16(acc[mi][ni], a[mi], b[ni]);
        }
        __syncthreads();
    }

    const float inv = rsqrtf(1.0f + 1e-5f);
    #pragma unroll
    for (int ni = 0; ni < 4; ni++) {
        int gn = n0 + warp_n * 32 + ni * 8 + tig * 2;
        float bi0 = 0.f, bi1 = 0.f, sc0 = 0.f, sc1 = 0.f, bb0 = 0.f, bb1 = 0.f;
        if (MODE == 1) {
            bi0 = __ldg(&bias[gn]);      bi1 = __ldg(&bias[gn + 1]);
            sc0 = __ldg(&bng[gn]) * inv; sc1 = __ldg(&bng[gn + 1]) * inv;
            bb0 = __ldg(&bnb[gn]);       bb1 = __ldg(&bnb[gn + 1]);
        }
        #pragma unroll
        for (int mi = 0; mi < 2; mi++) {
            int r0 = m0 + warp_m * 32 + mi * 16 + gid;
            #pragma unroll
            for (int h = 0; h < 2; h++) {
                int gm = r0 + h * 8;
                if (gm < M) {
                    float v0 = acc[mi][ni][h * 2 + 0];
                    float v1 = acc[mi][ni][h * 2 + 1];
                    if (MODE == 1) {
                        v0 = fmaxf(fmaf(v0 + bi0, sc0, bb0), 0.f);
                        v1 = fmaxf(fmaf(v1 + bi1, sc1, bb1), 0.f);
                    }
                    if (OUT == 1) {
                        ((uint32_t*)C)[(size_t)gm * (NC >> 1) + (gn >> 1)] = bfpack(v0, v1);
                    } else if (OUT == 2) {
                        ((uint32_t*)C)[(size_t)gm * (NC >> 1) + (gn >> 1)] = hfpack(v0, v1);
                    } else {
                        *(float2*)&((float*)C)[(size_t)gm * NC + gn] = make_float2(v0, v1);
                    }
                }
            }
        }
    }
}

// ---------------- driver ----------------
extern "C" void kernel_launch(void* const* d_in, const int* in_sizes, int n_in,
                              void* d_out, int out_size) {
    const float* x   = (const float*)d_in[0];
    const void*  ei  = d_in[1];
    const float* ew  = (const float*)d_in[2];
    const float* W0  = (const float*)d_in[3];
    const float* b0  = (const float*)d_in[4];
    const float* W1  = (const float*)d_in[5];
    const float* b1  = (const float*)d_in[6];
    const float* Wl  = (const float*)d_in[7];
    const float* bl  = (const float*)d_in[8];
    const float* g0  = (const float*)d_in[9];
    const float* be0 = (const float*)d_in[10];
    const float* g1  = (const float*)d_in[11];
    const float* be1 = (const float*)d_in[12];
    float* out = (float*)d_out;

    float *bufA = nullptr, *bufB = nullptr;
    uint16_t *wt0 = nullptr, *wt1 = nullptr, *wt2 = nullptr;
    cudaGetSymbolAddress((void**)&bufA, g_bufA);
    cudaGetSymbolAddress((void**)&bufB, g_bufB);
    cudaGetSymbolAddress((void**)&wt0, g_wt0);
    cudaGetSymbolAddress((void**)&wt1, g_wt1);
    cudaGetSymbolAddress((void**)&wt2, g_wt2);
    uint32_t* wA = (uint32_t*)bufA;
    uint32_t* wB = (uint32_t*)bufB;

    const int NB_E = (N_EDGES + 255) / 256;
    const int NB_W = (N_NODES * 32 + 255) / 256;
    const int MT   = (N_NODES + 127) / 128;

    // fused pre (detect + init + x->bf16 into wB) and weight transposes
    k_pre<<<NB_INIT + NB_CVT, 256>>>((const int*)ei, x, wB);
    k_transpose_all<<<128, dim3(32, 8)>>>(W0, W1, Wl);

    // graph build
    k_degcount<<<NB_E, 256>>>(ei, ew);
    k_scan1<<<SCAN_NB, SCAN_B>>>();
    k_scan2<<<1, 32>>>();
    k_scan3<<<NB_INIT, 256>>>();
    k_scatter<<<NB_E, 256>>>(ei, ew);

    // layer 0: agg_bf(x_bf)[N,128] wB -> wA; bf16 GEMM 128->256 -> wB
    k_agg_bf<2><<<NB_W, 256>>>(wB, wA);
    k_gemm_bf<128, 1, 1><<<dim3(MT, DIM_HID / 64), 256>>>(
        wA, wt0, wB, N_NODES, DIM_HID, b0, g0, be0);

    // layer 1: agg_bf[N,256] wB -> wA; bf16 GEMM 256->256 -> wB
    k_agg_bf<4><<<NB_W, 256>>>(wB, wA);
    k_gemm_bf<256, 1, 1><<<dim3(MT, DIM_HID / 64), 256>>>(
        wA, wt1, wB, N_NODES, DIM_HID, b1, g1, be1);

    // layer 2: bf16 GEMM 256->128 (plain, fp16 out) wB -> wA; fused agg+softmax
    k_gemm_bf<256, 0, 2><<<dim3(MT, DIM_OUT / 64), 256>>>(
        wB, wt2, wA, N_NODES, DIM_OUT, nullptr, nullptr, nullptr);
    k_agg_softmax<<<NB_W, 256>>>(wA, bl, out);
}

// round 14
// speedup vs baseline: 2.3643x; 1.0600x over previous
#include <cuda_runtime.h>
#include <cuda_fp16.h>
#include <cstdint>

#define N_NODES 50000
#define N_EDGES 800000
#define DIM_IN  128
#define DIM_HID 256
#define DIM_OUT 128
#define SCAN_B  512
#define SCAN_NB 98   // ceil(50000/512)

// ---------------- scratch (no allocations allowed) ----------------
__device__ __align__(16) float g_bufA[N_NODES * DIM_HID];   // 51.2 MB
__device__ __align__(16) float g_bufB[N_NODES * DIM_HID];   // 51.2 MB
__device__ __align__(16) uint16_t g_wt0[DIM_IN  * DIM_HID];
__device__ __align__(16) uint16_t g_wt1[DIM_HID * DIM_HID];
__device__ __align__(16) uint16_t g_wt2[DIM_HID * DIM_OUT];
__device__ float g_deg[N_NODES];
__device__ float g_dinv[N_NODES];
__device__ int   g_count[N_NODES];
__device__ int   g_indptr[N_NODES];
__device__ int   g_cursor[N_NODES];
__device__ int   g_blocksums[SCAN_NB];
__device__ int   g_esrc[N_EDGES];
__device__ float g_enorm[N_EDGES];
__device__ int   g_i64;

__device__ __forceinline__ int clampi(int v) {
    return min(max(v, 0), N_NODES - 1);
}
__device__ __forceinline__ int eidx(const void* ei, int j, int e) {
    if (g_i64) return clampi((int)((const long long*)ei)[j * N_EDGES + e]);
    return clampi(((const int*)ei)[j * N_EDGES + e]);
}

// bf16 helpers (bf16x2 packed in uint32: lo = lower address element)
__device__ __forceinline__ float bflo(uint32_t u) { return __uint_as_float(u << 16); }
__device__ __forceinline__ float bfhi(uint32_t u) { return __uint_as_float(u & 0xffff0000u); }
__device__ __forceinline__ uint32_t bfpack(float lo, float hi) {
    uint32_t r;
    asm("cvt.rn.bf16x2.f32 %0, %1, %2;" : "=r"(r) : "f"(hi), "f"(lo));
    return r;
}
__device__ __forceinline__ uint16_t bf1(float f) {
    uint16_t r;
    asm("cvt.rn.bf16.f32 %0, %1;" : "=h"(r) : "f"(f));
    return r;
}
__device__ __forceinline__ uint32_t hfpack(float lo, float hi) {
    uint32_t r;
    asm("cvt.rn.f16x2.f32 %0, %1, %2;" : "=r"(r) : "f"(hi), "f"(lo));
    return r;
}
__device__ __forceinline__ void mma_bf16(float* c, const uint32_t* a, const uint32_t* b) {
    asm volatile(
        "mma.sync.aligned.m16n8k16.row.col.f32.bf16.bf16.f32 "
        "{%0,%1,%2,%3}, {%4,%5,%6,%7}, {%8,%9}, {%0,%1,%2,%3};"
        : "+f"(c[0]), "+f"(c[1]), "+f"(c[2]), "+f"(c[3])
        : "r"(a[0]), "r"(a[1]), "r"(a[2]), "r"(a[3]), "r"(b[0]), "r"(b[1]));
}

// ---------------- fused: dtype detect (block 0) + init + x->bf16 ----------------
#define NB_INIT 196                       // ceil(50000/256)
#define NB_CVT  12500                     // 50000*64/256 words
__global__ void k_pre(const int* __restrict__ ei32,
                      const float* __restrict__ x, uint32_t* __restrict__ xb) {
    int bid = blockIdx.x;
    if (bid == 0) {
        __shared__ int s_nz;
        if (threadIdx.x == 0) s_nz = 0;
        __syncthreads();
        int nz = 0;
        for (int t = threadIdx.x; t < 2048; t += blockDim.x)
            if (ei32[2 * t + 1] != 0) nz = 1;
        if (nz) atomicOr(&s_nz, 1);
        __syncthreads();
        if (threadIdx.x == 0) g_i64 = (s_nz == 0) ? 1 : 0;
    }
    if (bid < NB_INIT) {
        int i = bid * 256 + threadIdx.x;
        if (i < N_NODES) { g_deg[i] = 1.0f; g_count[i] = 0; }
    } else {
        int i = (bid - NB_INIT) * 256 + threadIdx.x;
        if (i < N_NODES * (DIM_IN / 2)) {
            float2 v = ((const float2*)x)[i];
            xb[i] = bfpack(v.x, v.y);
        }
    }
}

// ---------------- graph build ----------------
__global__ void k_degcount(const void* __restrict__ ei,
                           const float* __restrict__ ew) {
    int e = blockIdx.x * blockDim.x + threadIdx.x;
    if (e < N_EDGES) {
        int c = eidx(ei, 1, e);
        atomicAdd(&g_deg[c], ew[e]);
        atomicAdd(&g_count[c], 1);
    }
}

__global__ void k_scan1() {
    __shared__ int sh[SCAN_B];
    int tid = threadIdx.x;
    int i = blockIdx.x * SCAN_B + tid;
    int v = (i < N_NODES) ? g_count[i] : 0;
    sh[tid] = v;
    __syncthreads();
    #pragma unroll
    for (int off = 1; off < SCAN_B; off <<= 1) {
        int t = (tid >= off) ? sh[tid - off] : 0;
        __syncthreads();
        sh[tid] += t;
        __syncthreads();
    }
    if (i < N_NODES) g_indptr[i] = sh[tid] - v;
    if (tid == SCAN_B - 1) g_blocksums[blockIdx.x] = sh[SCAN_B - 1];
}

__global__ void k_scan2() {
    if (threadIdx.x == 0) {
        int s = 0;
        for (int b = 0; b < SCAN_NB; b++) {
            int t = g_blocksums[b];
            g_blocksums[b] = s;
            s += t;
        }
    }
}

__global__ void k_scan3() {      // + dinv fused
    int i = blockIdx.x * blockDim.x + threadIdx.x;
    if (i < N_NODES) {
        int p = g_indptr[i] + g_blocksums[i >> 9];
        g_indptr[i] = p;
        g_cursor[i] = p;
        g_dinv[i] = rsqrtf(g_deg[i]);
    }
}

__global__ void k_scatter(const void* __restrict__ ei,
                          const float* __restrict__ ew) {
    int e = blockIdx.x * blockDim.x + threadIdx.x;
    if (e < N_EDGES) {
        int r = eidx(ei, 0, e);
        int c = eidx(ei, 1, e);
        int pos = atomicAdd(&g_cursor[c], 1);
        g_esrc[pos] = r;
        g_enorm[pos] = g_dinv[r] * ew[e] * g_dinv[c];
    }
}

// ---------------- bf16 aggregation (warp per node, W words per lane, 4x unroll) ----
template <int W>
__global__ void k_agg_bf(const uint32_t* __restrict__ src, uint32_t* __restrict__ dst) {
    int gw = (blockIdx.x * blockDim.x + threadIdx.x) >> 5;
    int lane = threadIdx.x & 31;
    if (gw >= N_NODES) return;
    const int rs = W * 32;
    const uint32_t* sl = src + lane * W;           // lane-offset base
    float dn = g_dinv[gw], sw = dn * dn;
    uint32_t u[W];
    {
        const uint32_t* p = sl + (size_t)gw * rs;
        if (W == 4) *(uint4*)u = *(const uint4*)p; else *(uint2*)u = *(const uint2*)p;
    }
    float acc[2 * W];
    #pragma unroll
    for (int w = 0; w < W; w++) {
        acc[2 * w]     = sw * bflo(u[w]);
        acc[2 * w + 1] = sw * bfhi(u[w]);
    }
    int i = g_indptr[gw];
    int end = i + g_count[gw];
    for (; i + 4 <= end; i += 4) {
        int r0 = g_esrc[i],     r1 = g_esrc[i + 1];
        int r2 = g_esrc[i + 2], r3 = g_esrc[i + 3];
        float w0 = g_enorm[i],     w1 = g_enorm[i + 1];
        float w2 = g_enorm[i + 2], w3 = g_enorm[i + 3];
        uint32_t u0[W], u1[W], u2[W], u3[W];
        if (W == 4) {
            *(uint4*)u0 = *(const uint4*)(sl + (size_t)r0 * rs);
            *(uint4*)u1 = *(const uint4*)(sl + (size_t)r1 * rs);
            *(uint4*)u2 = *(const uint4*)(sl + (size_t)r2 * rs);
            *(uint4*)u3 = *(const uint4*)(sl + (size_t)r3 * rs);
        } else {
            *(uint2*)u0 = *(const uint2*)(sl + (size_t)r0 * rs);
            *(uint2*)u1 = *(const uint2*)(sl + (size_t)r1 * rs);
            *(uint2*)u2 = *(const uint2*)(sl + (size_t)r2 * rs);
            *(uint2*)u3 = *(const uint2*)(sl + (size_t)r3 * rs);
        }
        #pragma unroll
        for (int w = 0; w < W; w++) {
            acc[2 * w]     += w0 * bflo(u0[w]) + w1 * bflo(u1[w])
                            + w2 * bflo(u2[w]) + w3 * bflo(u3[w]);
            acc[2 * w + 1] += w0 * bfhi(u0[w]) + w1 * bfhi(u1[w])
                            + w2 * bfhi(u2[w]) + w3 * bfhi(u3[w]);
        }
    }
    for (; i < end; i++) {
        int r0 = g_esrc[i];
        float w0 = g_enorm[i];
        uint32_t u0[W];
        if (W == 4) *(uint4*)u0 = *(const uint4*)(sl + (size_t)r0 * rs);
        else        *(uint2*)u0 = *(const uint2*)(sl + (size_t)r0 * rs);
        #pragma unroll
        for (int w = 0; w < W; w++) {
            acc[2 * w]     += w0 * bflo(u0[w]);
            acc[2 * w + 1] += w0 * bfhi(u0[w]);
        }
    }
    uint32_t o[W];
    #pragma unroll
    for (int w = 0; w < W; w++) o[w] = bfpack(acc[2 * w], acc[2 * w + 1]);
    uint32_t* q = dst + (size_t)gw * rs + lane * W;
    if (W == 4) *(uint4*)q = *(const uint4*)o; else *(uint2*)q = *(const uint2*)o;
}

// ---------------- fused final: fp16 agg (dim 128) + bias + log_softmax ----------------
__global__ void k_agg_softmax(const uint32_t* __restrict__ src,
                              const float* __restrict__ bl,
                              float* __restrict__ out) {
    int gw = (blockIdx.x * blockDim.x + threadIdx.x) >> 5;
    int lane = threadIdx.x & 31;
    if (gw >= N_NODES) return;
    const int rs = 64;
    const uint32_t* sl = src + lane * 2;
    float dn = g_dinv[gw], sw = dn * dn;
    float acc[4];
    {
        uint2 u = *(const uint2*)(sl + (size_t)gw * rs);
        float2 a = __half22float2(*(__half2*)&u.x);
        float2 b = __half22float2(*(__half2*)&u.y);
        acc[0] = sw * a.x; acc[1] = sw * a.y; acc[2] = sw * b.x; acc[3] = sw * b.y;
    }
    int i = g_indptr[gw];
    int end = i + g_count[gw];
    for (; i + 4 <= end; i += 4) {
        int r0 = g_esrc[i],     r1 = g_esrc[i + 1];
        int r2 = g_esrc[i + 2], r3 = g_esrc[i + 3];
        float w0 = g_enorm[i],     w1 = g_enorm[i + 1];
        float w2 = g_enorm[i + 2], w3 = g_enorm[i + 3];
        uint2 u0 = *(const uint2*)(sl + (size_t)r0 * rs);
        uint2 u1 = *(const uint2*)(sl + (size_t)r1 * rs);
        uint2 u2 = *(const uint2*)(sl + (size_t)r2 * rs);
        uint2 u3 = *(const uint2*)(sl + (size_t)r3 * rs);
        float2 a0 = __half22float2(*(__half2*)&u0.x), b0 = __half22float2(*(__half2*)&u0.y);
        float2 a1 = __half22float2(*(__half2*)&u1.x), b1 = __half22float2(*(__half2*)&u1.y);
        float2 a2 = __half22float2(*(__half2*)&u2.x), b2 = __half22float2(*(__half2*)&u2.y);
        float2 a3 = __half22float2(*(__half2*)&u3.x), b3 = __half22float2(*(__half2*)&u3.y);
        acc[0] += w0 * a0.x + w1 * a1.x + w2 * a2.x + w3 * a3.x;
        acc[1] += w0 * a0.y + w1 * a1.y + w2 * a2.y + w3 * a3.y;
        acc[2] += w0 * b0.x + w1 * b1.x + w2 * b2.x + w3 * b3.x;
        acc[3] += w0 * b0.y + w1 * b1.y + w2 * b2.y + w3 * b3.y;
    }
    for (; i < end; i++) {
        int r0 = g_esrc[i];
        float w0 = g_enorm[i];
        uint2 u0 = *(const uint2*)(sl + (size_t)r0 * rs);
        float2 a0 = __half22float2(*(__half2*)&u0.x);
        float2 b0 = __half22float2(*(__half2*)&u0.y);
        acc[0] += w0 * a0.x; acc[1] += w0 * a0.y;
        acc[2] += w0 * b0.x; acc[3] += w0 * b0.y;
    }
    float4 b = ((const float4*)bl)[lane];
    acc[0] += b.x; acc[1] += b.y; acc[2] += b.z; acc[3] += b.w;
    float m = fmaxf(fmaxf(acc[0], acc[1]), fmaxf(acc[2], acc[3]));
    #pragma unroll
    for (int o = 16; o; o >>= 1) m = fmaxf(m, __shfl_xor_sync(0xFFFFFFFFu, m, o));
    float s = expf(acc[0] - m) + expf(acc[1] - m) + expf(acc[2] - m) + expf(acc[3] - m);
    #pragma unroll
    for (int o = 16; o; o >>= 1) s += __shfl_xor_sync(0xFFFFFFFFu, s, o);
    float lse = m + logf(s);
    float4 o4 = make_float4(acc[0] - lse, acc[1] - lse, acc[2] - lse, acc[3] - lse);
    ((float4*)out)[gw * 32 + lane] = o4;
}

// ---------------- fused weight transposes: Wt[NC][K] = bf16(W[K][NC]) ----------------
__global__ void k_transpose_all(const float* __restrict__ W0,
                                const float* __restrict__ W1,
                                const float* __restrict__ Wl) {
    __shared__ float t[32][33];
    int bid = blockIdx.x;
    const float* W; uint16_t* D; int K, NC, tk, tn;
    if (bid < 32)      { W = W0; D = g_wt0; K = DIM_IN;  NC = DIM_HID; int b = bid;      tk = b & 3; tn = b >> 2; }
    else if (bid < 96) { W = W1; D = g_wt1; K = DIM_HID; NC = DIM_HID; int b = bid - 32; tk = b & 7; tn = b >> 3; }
    else               { W = Wl; D = g_wt2; K = DIM_HID; NC = DIM_OUT; int b = bid - 96; tk = b & 7; tn = b >> 3; }
    int bx = tk * 32, by = tn * 32;
    int x = threadIdx.x, y = threadIdx.y;
    for (int i = y; i < 32; i += 8)
        t[i][x] = W[(size_t)(bx + i) * NC + by + x];
    __syncthreads();
    for (int i = y; i < 32; i += 8)
        D[(size_t)(by + i) * K + bx + x] = bf1(t[x][i]);
}

// ---------------- bf16 mma.sync GEMM, BM=128 BN=128 BK=64 ----------------
// 8 warps (4m x 2n), warp tile 32x64 (2mi x 8ni m16n8k16 frags).
// OUT: 0 = fp32, 1 = bf16-packed, 2 = fp16-packed
#define SPAD 36
template <int K_, int MODE, int OUT>
__global__ __launch_bounds__(256) void k_gemm_bf(
    const uint32_t* __restrict__ A, const uint16_t* __restrict__ Bw16,
    void* __restrict__ C, int M, int NC,
    const float* __restrict__ bias, const float* __restrict__ bng,
    const float* __restrict__ bnb) {
    __shared__ uint32_t As[128 * SPAD];
    __shared__ uint32_t Bs[128 * SPAD];
    const int tid = threadIdx.x;
    const int wid = tid >> 5;
    const int lane = tid & 31;
    const int gid = lane >> 2;
    const int tig = lane & 3;
    const int warp_m = wid & 3;
    const int warp_n = wid >> 2;
    const int m0 = blockIdx.x * 128;
    const int n0 = blockIdx.y * 128;
    const int KW = K_ >> 1;
    const uint32_t* Bw = (const uint32_t*)Bw16;

    float acc[2][8][4];
    #pragma unroll
    for (int mi = 0; mi < 2; mi++)
        #pragma unroll
        for (int ni = 0; ni < 8; ni++)
            #pragma unroll
            for (int j = 0; j < 4; j++) acc[mi][ni][j] = 0.f;

    #pragma unroll 1
    for (int kt = 0; kt < KW; kt += 32) {
        #pragma unroll
        for (int l = 0; l < 4; l++) {
            int t = tid + l * 256;
            int r = t >> 3, q = t & 7;
            int gm = m0 + r;
            uint4 v = make_uint4(0u, 0u, 0u, 0u);
            if (gm < M) v = *(const uint4*)&A[(size_t)gm * KW + kt + q * 4];
            *(uint4*)&As[r * SPAD + q * 4] = v;
        }
        #pragma unroll
        for (int l = 0; l < 4; l++) {
            int t = tid + l * 256;
            int r = t >> 3, q = t & 7;
            uint4 v = *(const uint4*)&Bw[(size_t)(n0 + r) * KW + kt + q * 4];
            *(uint4*)&Bs[r * SPAD + q * 4] = v;
        }
        __syncthreads();

        #pragma unroll
        for (int g8 = 0; g8 < 32; g8 += 8) {
            uint32_t a[2][4], b[8][2];
            #pragma unroll
            for (int mi = 0; mi < 2; mi++) {
                int mlo = warp_m * 32 + mi * 16 + gid;
                a[mi][0] = As[mlo * SPAD + g8 + tig];
                a[mi][1] = As[(mlo + 8) * SPAD + g8 + tig];
                a[mi][2] = As[mlo * SPAD + g8 + tig + 4];
                a[mi][3] = As[(mlo + 8) * SPAD + g8 + tig + 4];
            }
            #pragma unroll
            for (int ni = 0; ni < 8; ni++) {
                int n = warp_n * 64 + ni * 8 + gid;
                b[ni][0] = Bs[n * SPAD + g8 + tig];
                b[ni][1] = Bs[n * SPAD + g8 + tig + 4];
            }
            #pragma unroll
            for (int mi = 0; mi < 2; mi++)
                #pragma unroll
                for (int ni = 0; ni < 8; ni++)
                    mma_bf16(acc[mi][ni], a[mi], b[ni]);
        }
        __syncthreads();
    }

    const float inv = rsqrtf(1.0f + 1e-5f);
    #pragma unroll
    for (int ni = 0; ni < 8; ni++) {
        int gn = n0 + warp_n * 64 + ni * 8 + tig * 2;
        float bi0 = 0.f, bi1 = 0.f, sc0 = 0.f, sc1 = 0.f, bb0 = 0.f, bb1 = 0.f;
        if (MODE == 1) {
            bi0 = __ldg(&bias[gn]);      bi1 = __ldg(&bias[gn + 1]);
            sc0 = __ldg(&bng[gn]) * inv; sc1 = __ldg(&bng[gn + 1]) * inv;
            bb0 = __ldg(&bnb[gn]);       bb1 = __ldg(&bnb[gn + 1]);
        }
        #pragma unroll
        for (int mi = 0; mi < 2; mi++) {
            int r0 = m0 + warp_m * 32 + mi * 16 + gid;
            #pragma unroll
            for (int h = 0; h < 2; h++) {
                int gm = r0 + h * 8;
                if (gm < M) {
                    float v0 = acc[mi][ni][h * 2 + 0];
                    float v1 = acc[mi][ni][h * 2 + 1];
                    if (MODE == 1) {
                        v0 = fmaxf(fmaf(v0 + bi0, sc0, bb0), 0.f);
                        v1 = fmaxf(fmaf(v1 + bi1, sc1, bb1), 0.f);
                    }
                    if (OUT == 1) {
                        ((uint32_t*)C)[(size_t)gm * (NC >> 1) + (gn >> 1)] = bfpack(v0, v1);
                    } else if (OUT == 2) {
                        ((uint32_t*)C)[(size_t)gm * (NC >> 1) + (gn >> 1)] = hfpack(v0, v1);
                    } else {
                        *(float2*)&((float*)C)[(size_t)gm * NC + gn] = make_float2(v0, v1);
                    }
                }
            }
        }
    }
}

// ---------------- driver ----------------
extern "C" void kernel_launch(void* const* d_in, const int* in_sizes, int n_in,
                              void* d_out, int out_size) {
    const float* x   = (const float*)d_in[0];
    const void*  ei  = d_in[1];
    const float* ew  = (const float*)d_in[2];
    const float* W0  = (const float*)d_in[3];
    const float* b0  = (const float*)d_in[4];
    const float* W1  = (const float*)d_in[5];
    const float* b1  = (const float*)d_in[6];
    const float* Wl  = (const float*)d_in[7];
    const float* bl  = (const float*)d_in[8];
    const float* g0  = (const float*)d_in[9];
    const float* be0 = (const float*)d_in[10];
    const float* g1  = (const float*)d_in[11];
    const float* be1 = (const float*)d_in[12];
    float* out = (float*)d_out;

    float *bufA = nullptr, *bufB = nullptr;
    uint16_t *wt0 = nullptr, *wt1 = nullptr, *wt2 = nullptr;
    cudaGetSymbolAddress((void**)&bufA, g_bufA);
    cudaGetSymbolAddress((void**)&bufB, g_bufB);
    cudaGetSymbolAddress((void**)&wt0, g_wt0);
    cudaGetSymbolAddress((void**)&wt1, g_wt1);
    cudaGetSymbolAddress((void**)&wt2, g_wt2);
    uint32_t* wA = (uint32_t*)bufA;
    uint32_t* wB = (uint32_t*)bufB;

    const int NB_E = (N_EDGES + 255) / 256;
    const int NB_W = (N_NODES * 32 + 255) / 256;
    const int MT   = (N_NODES + 127) / 128;

    // fused pre (detect + init + x->bf16 into wB) and weight transposes
    k_pre<<<NB_INIT + NB_CVT, 256>>>((const int*)ei, x, wB);
    k_transpose_all<<<128, dim3(32, 8)>>>(W0, W1, Wl);

    // graph build
    k_degcount<<<NB_E, 256>>>(ei, ew);
    k_scan1<<<SCAN_NB, SCAN_B>>>();
    k_scan2<<<1, 32>>>();
    k_scan3<<<NB_INIT, 256>>>();
    k_scatter<<<NB_E, 256>>>(ei, ew);

    // layer 0: agg_bf(x_bf)[N,128] wB -> wA; bf16 GEMM 128->256 -> wB
    k_agg_bf<2><<<NB_W, 256>>>(wB, wA);
    k_gemm_bf<128, 1, 1><<<dim3(MT, DIM_HID / 128), 256>>>(
        wA, wt0, wB, N_NODES, DIM_HID, b0, g0, be0);

    // layer 1: agg_bf[N,256] wB -> wA; bf16 GEMM 256->256 -> wB
    k_agg_bf<4><<<NB_W, 256>>>(wB, wA);
    k_gemm_bf<256, 1, 1><<<dim3(MT, DIM_HID / 128), 256>>>(
        wA, wt1, wB, N_NODES, DIM_HID, b1, g1, be1);

    // layer 2: bf16 GEMM 256->128 (plain, fp16 out) wB -> wA; fused agg+softmax
    k_gemm_bf<256, 0, 2><<<dim3(MT, DIM_OUT / 128), 256>>>(
        wB, wt2, wA, N_NODES, DIM_OUT, nullptr, nullptr, nullptr);
    k_agg_softmax<<<NB_W, 256>>>(wA, bl, out);
}